// round 12
// baseline (speedup 1.0000x reference)
#include <cuda_runtime.h>

#define FEATURES 512
#define NB 64
#define NKNOTS 68
#define BATCH 2048
#define WIN 5

// P1 (sequential left-fold) coefficients, rows padded to 8 floats.
__device__ float g_coef[FEATURES * NB * 8];

__global__ void coef_kernel(const float* __restrict__ knots) {
    int idx = blockIdx.x * blockDim.x + threadIdx.x;   // idx = f*NB + i
    if (idx >= FEATURES * NB) return;
    const float* kr = knots + (idx / NB) * NKNOTS + (idx % NB);
    float kw[WIN];
#pragma unroll
    for (int j = 0; j < WIN; j++) kw[j] = kr[j];
#pragma unroll
    for (int j = 0; j < WIN; j++) {
        float p = 1.0f;
#pragma unroll
        for (int jp = 0; jp < WIN; jp++) {
            float d = (jp == j) ? 1.0f : __fsub_rn(kw[jp], kw[j]);
            p = __fmul_rn(p, d);          // P1: sequential (1*d0 exact, then fold)
        }
        g_coef[idx * 8 + j] = __fdiv_rn(1.0f, p);
    }
}

__global__ void __launch_bounds__(256)
bspline_kernel(const float* __restrict__ X,
               const float* __restrict__ knots,
               const float* __restrict__ W,
               float* __restrict__ out) {
    __shared__ float sk[NKNOTS + 4];
    __shared__ __align__(16) float sc[NB * 8];
    __shared__ float sw[NB];

    const int f = blockIdx.y;
    const int t = threadIdx.x;

    if (t < NKNOTS + 4) sk[t] = (t < NKNOTS) ? knots[f * NKNOTS + t] : 0.0f;
    if (t < NB)         sw[t] = W[f * NB + t];
    for (int u = t; u < NB * 8; u += 256)
        sc[u] = g_coef[f * NB * 8 + u];
    __syncthreads();

    const int b = blockIdx.x * 256 + t;
    const float x = X[b * FEATURES + f];

    float acc = 0.0f;
    float k0 = sk[0], k1 = sk[1], k2 = sk[2], k3 = sk[3], k4 = sk[4];

#pragma unroll 4
    for (int i = 0; i < NB; i++) {
        if (x <= k0) break;   // all later windows contribute exact zeros

        const float4 c03 = *reinterpret_cast<const float4*>(&sc[i * 8]);
        const float  c4  = sc[i * 8 + 4];

        float r, r3, t0, t1, t2, t3, t4;
        r  = fmaxf(__fsub_rn(x, k0), 0.0f);
        r3 = __fmul_rn(__fmul_rn(r, r), r);
        t0 = __fmul_rn(r3, c03.x);

        r  = fmaxf(__fsub_rn(x, k1), 0.0f);
        r3 = __fmul_rn(__fmul_rn(r, r), r);
        t1 = __fmul_rn(r3, c03.y);

        r  = fmaxf(__fsub_rn(x, k2), 0.0f);
        r3 = __fmul_rn(__fmul_rn(r, r), r);
        t2 = __fmul_rn(r3, c03.z);

        r  = fmaxf(__fsub_rn(x, k3), 0.0f);
        r3 = __fmul_rn(__fmul_rn(r, r), r);
        t3 = __fmul_rn(r3, c03.w);

        r  = fmaxf(__fsub_rn(x, k4), 0.0f);
        r3 = __fmul_rn(__fmul_rn(r, r), r);
        t4 = __fmul_rn(r3, c4);

        // S3: XLA:GPU multi-row warp reduce, 8 lanes/row, shfl-down 4,2,1:
        //   lane0: (t0+t4), then +t2, then +(t1+t3)
        float s = __fadd_rn(__fadd_rn(__fadd_rn(t0, t4), t2),
                            __fadd_rn(t1, t3));

        acc = __fadd_rn(acc, __fmul_rn(s, sw[i]));

        k0 = k1; k1 = k2; k2 = k3; k3 = k4; k4 = sk[i + 5];
    }

    out[b * FEATURES + f] = acc;
}

extern "C" void kernel_launch(void* const* d_in, const int* in_sizes, int n_in,
                              void* d_out, int out_size) {
    const float* x     = (const float*)d_in[0];
    const float* knots = (const float*)d_in[1];
    const float* w     = (const float*)d_in[2];
    float* out         = (float*)d_out;
    (void)in_sizes; (void)n_in; (void)out_size;

    coef_kernel<<<(FEATURES * NB + 255) / 256, 256>>>(knots);

    dim3 grid(BATCH / 256, FEATURES);
    bspline_kernel<<<grid, 256>>>(x, knots, w, out);
}

// round 14
// speedup vs baseline: 1.0918x; 1.0918x over previous
#include <cuda_runtime.h>

#define FEATURES 512
#define NB 64
#define NKNOTS 68
#define BATCH 2048
#define NROW 65   // 64 splines + sentinel row

// Per (feature, spline) row, 2 x float4:
//   ra = (c0, c1, c2, c3)
//   rb = (c4, w, k_break = k[i], k_new = k[i+4])
// Sentinel row i=64: ra = (k0,k1,k2,k3) [prologue knots], rb = (0,0,2.0,0).
__device__ float4 g_rows[FEATURES * NROW * 2];

__global__ void prep_kernel(const float* __restrict__ knots,
                            const float* __restrict__ weights) {
    int idx = blockIdx.x * blockDim.x + threadIdx.x;   // f*NROW + i
    if (idx >= FEATURES * NROW) return;
    int f = idx / NROW, i = idx % NROW;
    const float* kr = knots + f * NKNOTS;
    float4 ra, rb;
    if (i < NB) {
        float kw[5];
#pragma unroll
        for (int j = 0; j < 5; j++) kw[j] = kr[i + j];
        float c[5];
#pragma unroll
        for (int j = 0; j < 5; j++) {
            float p = 1.0f;                       // P1: sequential left fold
#pragma unroll
            for (int jp = 0; jp < 5; jp++) {
                float d = (jp == j) ? 1.0f : __fsub_rn(kw[jp], kw[j]);
                p = __fmul_rn(p, d);
            }
            c[j] = __fdiv_rn(1.0f, p);
        }
        ra = make_float4(c[0], c[1], c[2], c[3]);
        rb = make_float4(c[4], weights[f * NB + i], kr[i], kr[i + 4]);
    } else {
        ra = make_float4(kr[0], kr[1], kr[2], kr[3]);
        rb = make_float4(0.0f, 0.0f, 2.0f, 0.0f);  // break-knot 2.0 > any x
    }
    g_rows[idx * 2 + 0] = ra;
    g_rows[idx * 2 + 1] = rb;
}

// cube with the exact rounding chain of the reference: (r*r)*r
__device__ __forceinline__ float cube_relu(float x, float k) {
    float r = fmaxf(__fsub_rn(x, k), 0.0f);
    return __fmul_rn(__fmul_rn(r, r), r);
}

__global__ void __launch_bounds__(256)
bspline_kernel(const float* __restrict__ X, float* __restrict__ out) {
    __shared__ __align__(16) float4 sr[NROW * 2];

    const int f = blockIdx.y;
    const int t = threadIdx.x;
    if (t < NROW * 2) sr[t] = g_rows[f * NROW * 2 + t];
    __syncthreads();

    const int b = blockIdx.x * 256 + t;
    const float x = X[b * FEATURES + f];

    // Prologue: r3 slots for knots k[0..3] (stored in sentinel row's ra).
    const float4 hk = sr[64 * 2 + 0];
    float r3v[5];
    r3v[0] = cube_relu(x, hk.x);
    r3v[1] = cube_relu(x, hk.y);
    r3v[2] = cube_relu(x, hk.z);
    r3v[3] = cube_relu(x, hk.w);
    r3v[4] = 0.0f;

    float acc = 0.0f;

#pragma unroll 5
    for (int i = 0; i < NROW; i++) {
        const float4 rb = sr[i * 2 + 1];       // c4, w, k_break, k_new
        if (x <= rb.z) break;                  // all later splines exact zero
        const float4 ra = sr[i * 2 + 0];       // c0..c3

        // one NEW relu+cube per spline (knot m = i+4), rest reused bit-exactly
        r3v[(i + 4) % 5] = cube_relu(x, rb.w);

        const float t0 = __fmul_rn(r3v[(i + 0) % 5], ra.x);
        const float t1 = __fmul_rn(r3v[(i + 1) % 5], ra.y);
        const float t2 = __fmul_rn(r3v[(i + 2) % 5], ra.z);
        const float t3 = __fmul_rn(r3v[(i + 3) % 5], ra.w);
        const float t4 = __fmul_rn(r3v[(i + 4) % 5], rb.x);

        // S3: ((t0+t4)+t2)+(t1+t3)
        const float s = __fadd_rn(__fadd_rn(__fadd_rn(t0, t4), t2),
                                  __fadd_rn(t1, t3));

        acc = __fadd_rn(acc, __fmul_rn(s, rb.y));
    }

    out[b * FEATURES + f] = acc;
}

extern "C" void kernel_launch(void* const* d_in, const int* in_sizes, int n_in,
                              void* d_out, int out_size) {
    const float* x     = (const float*)d_in[0];
    const float* knots = (const float*)d_in[1];
    const float* w     = (const float*)d_in[2];
    float* out         = (float*)d_out;
    (void)in_sizes; (void)n_in; (void)out_size;

    prep_kernel<<<(FEATURES * NROW + 255) / 256, 256>>>(knots, w);

    dim3 grid(BATCH / 256, FEATURES);
    bspline_kernel<<<grid, 256>>>(x, out);
}

// round 15
// speedup vs baseline: 1.1694x; 1.0711x over previous
#include <cuda_runtime.h>

#define FEATURES 512
#define NB 64
#define NKNOTS 68
#define BATCH 2048
#define NROW 65   // 64 splines + sentinel row

// Per (feature, spline) row, 2 x float4:
//   ra = (c0, c1, c2, c3)
//   rb = (c4, w, k_break = k[i], k_new = k[i+4])
// Sentinel row i=64: ra = (k0,k1,k2,k3) [prologue knots], rb = (0,0,2.0,0).
__device__ float4 g_rows[FEATURES * NROW * 2];
// Per-feature value-sorted batch: x values and original b indices.
__device__ float g_xs[FEATURES * BATCH];
__device__ int   g_pb[FEATURES * BATCH];

__global__ void prep_kernel(const float* __restrict__ knots,
                            const float* __restrict__ weights) {
    int idx = blockIdx.x * blockDim.x + threadIdx.x;   // f*NROW + i
    if (idx >= FEATURES * NROW) return;
    int f = idx / NROW, i = idx % NROW;
    const float* kr = knots + f * NKNOTS;
    float4 ra, rb;
    if (i < NB) {
        float kw[5];
#pragma unroll
        for (int j = 0; j < 5; j++) kw[j] = kr[i + j];
        float c[5];
#pragma unroll
        for (int j = 0; j < 5; j++) {
            float p = 1.0f;                       // P1: sequential left fold
#pragma unroll
            for (int jp = 0; jp < 5; jp++) {
                float d = (jp == j) ? 1.0f : __fsub_rn(kw[jp], kw[j]);
                p = __fmul_rn(p, d);
            }
            c[j] = __fdiv_rn(1.0f, p);
        }
        ra = make_float4(c[0], c[1], c[2], c[3]);
        rb = make_float4(c[4], weights[f * NB + i], kr[i], kr[i + 4]);
    } else {
        ra = make_float4(kr[0], kr[1], kr[2], kr[3]);
        rb = make_float4(0.0f, 0.0f, 2.0f, 0.0f);  // break-knot 2.0 > any x
    }
    g_rows[idx * 2 + 0] = ra;
    g_rows[idx * 2 + 1] = rb;
}

// Per-feature counting sort by bucket = floor(64x). Any permutation is
// bit-neutral for the output (each out depends only on its own x), so the
// nondeterministic within-bucket order from atomics is harmless.
__global__ void __launch_bounds__(256)
sort_kernel(const float* __restrict__ X) {
    __shared__ int hist[64];
    __shared__ int offs[64];
    const int f = blockIdx.x;
    const int t = threadIdx.x;

    if (t < 64) hist[t] = 0;
    __syncthreads();

    float xv[8];
    int   bk[8];
#pragma unroll
    for (int r = 0; r < 8; r++) {
        int b = r * 256 + t;
        float x = X[b * FEATURES + f];
        int k = (int)(x * 64.0f);
        k = min(max(k, 0), 63);
        xv[r] = x; bk[r] = k;
        atomicAdd(&hist[k], 1);
    }
    __syncthreads();

    if (t == 0) {
        int s = 0;
#pragma unroll
        for (int i = 0; i < 64; i++) { offs[i] = s; s += hist[i]; }
    }
    __syncthreads();

#pragma unroll
    for (int r = 0; r < 8; r++) {
        int pos = atomicAdd(&offs[bk[r]], 1);
        g_xs[f * BATCH + pos] = xv[r];
        g_pb[f * BATCH + pos] = r * 256 + t;
    }
}

// cube with the exact rounding chain of the reference: (r*r)*r
__device__ __forceinline__ float cube_relu(float x, float k) {
    float r = fmaxf(__fsub_rn(x, k), 0.0f);
    return __fmul_rn(__fmul_rn(r, r), r);
}

__global__ void __launch_bounds__(256)
bspline_kernel(float* __restrict__ out) {
    __shared__ __align__(16) float4 sr[NROW * 2];

    const int f = blockIdx.y;
    const int t = threadIdx.x;
    if (t < NROW * 2) sr[t] = g_rows[f * NROW * 2 + t];
    __syncthreads();

    const int slot = blockIdx.x * 256 + t;
    const float x = g_xs[f * BATCH + slot];     // coalesced, value-sorted
    const int   bo = g_pb[f * BATCH + slot];

    // Prologue: r3 slots for knots k[0..3] (stored in sentinel row's ra).
    const float4 hk = sr[64 * 2 + 0];
    float r3v[5];
    r3v[0] = cube_relu(x, hk.x);
    r3v[1] = cube_relu(x, hk.y);
    r3v[2] = cube_relu(x, hk.z);
    r3v[3] = cube_relu(x, hk.w);
    r3v[4] = 0.0f;

    float acc = 0.0f;

#pragma unroll 5
    for (int i = 0; i < NROW; i++) {
        const float4 rb = sr[i * 2 + 1];       // c4, w, k_break, k_new
        if (x <= rb.z) break;                  // all later splines exact zero
        const float4 ra = sr[i * 2 + 0];       // c0..c3

        // one NEW relu+cube per spline (knot m = i+4), rest reused bit-exactly
        r3v[(i + 4) % 5] = cube_relu(x, rb.w);

        const float t0 = __fmul_rn(r3v[(i + 0) % 5], ra.x);
        const float t1 = __fmul_rn(r3v[(i + 1) % 5], ra.y);
        const float t2 = __fmul_rn(r3v[(i + 2) % 5], ra.z);
        const float t3 = __fmul_rn(r3v[(i + 3) % 5], ra.w);
        const float t4 = __fmul_rn(r3v[(i + 4) % 5], rb.x);

        // S3: ((t0+t4)+t2)+(t1+t3)
        const float s = __fadd_rn(__fadd_rn(__fadd_rn(t0, t4), t2),
                                  __fadd_rn(t1, t3));

        acc = __fadd_rn(acc, __fmul_rn(s, rb.y));
    }

    out[bo * FEATURES + f] = acc;
}

extern "C" void kernel_launch(void* const* d_in, const int* in_sizes, int n_in,
                              void* d_out, int out_size) {
    const float* x     = (const float*)d_in[0];
    const float* knots = (const float*)d_in[1];
    const float* w     = (const float*)d_in[2];
    float* out         = (float*)d_out;
    (void)in_sizes; (void)n_in; (void)out_size;

    prep_kernel<<<(FEATURES * NROW + 255) / 256, 256>>>(knots, w);
    sort_kernel<<<FEATURES, 256>>>(x);

    dim3 grid(BATCH / 256, FEATURES);
    bspline_kernel<<<grid, 256>>>(out);
}